// round 13
// baseline (speedup 1.0000x reference)
#include <cuda_runtime.h>
#include <cuda_bf16.h>
#include <stdint.h>

#define C_IN   32
#define C_OUT  32
#define KD     27
#define TPB    128
#define TM     128
#define MAXN   262144
#define ARS    144                   // A row stride (bytes): conflict-free ldsm

// ---------------- device scratch ----------------
__device__ __align__(256) __nv_bfloat16 g_pack[(MAXN + 1) * 64]; // [N+1][128B] hi|lo; row N zeros
__device__ __align__(256) uint2 g_bfrag[KD * 16 * 32];           // [k][frag][lane], 4KB/k
__device__ __align__(256) int g_nT[KD * MAXN];                   // [k][node]: clamped offset<<7
__device__ int g_neigh_is64;

// ---------------- helpers ----------------
__device__ __forceinline__ uint32_t s2u(const void* p) {
    uint32_t a;
    asm("{ .reg .u64 t; cvta.to.shared.u64 t, %1; cvt.u32.u64 %0, t; }" : "=r"(a) : "l"(p));
    return a;
}
__device__ __forceinline__ void bulkcp(uint32_t dst, const void* src, uint32_t bytes, uint32_t mbar) {
    asm volatile("cp.async.bulk.shared::cluster.global.mbarrier::complete_tx::bytes "
                 "[%0], [%1], %2, [%3];"
                 :: "r"(dst), "l"(src), "r"(bytes), "r"(mbar) : "memory");
}
__device__ __forceinline__ void cpasync16(uint32_t dst, const void* src) {
    asm volatile("cp.async.cg.shared.global [%0], [%1], 16;" :: "r"(dst), "l"(src));
}
__device__ __forceinline__ void ldsm4(uint32_t* r, uint32_t addr) {
    asm volatile("ldmatrix.sync.aligned.m8n8.x4.shared.b16 {%0,%1,%2,%3}, [%4];"
                 : "=r"(r[0]), "=r"(r[1]), "=r"(r[2]), "=r"(r[3]) : "r"(addr));
}
__device__ __forceinline__ void mma16816(float* c, const uint32_t* a, uint2 b) {
    asm volatile("mma.sync.aligned.m16n8k16.row.col.f32.bf16.bf16.f32 "
                 "{%0,%1,%2,%3}, {%4,%5,%6,%7}, {%8,%9}, {%0,%1,%2,%3};"
                 : "+f"(c[0]), "+f"(c[1]), "+f"(c[2]), "+f"(c[3])
                 : "r"(a[0]), "r"(a[1]), "r"(a[2]), "r"(a[3]), "r"(b.x), "r"(b.y));
}
#define MBAR_WAIT(addr, ph) do {                                                      \
    asm volatile("{\n\t.reg .pred P1;\n\t"                                            \
        "WAIT_%=:\n\t"                                                                \
        "mbarrier.try_wait.parity.acquire.cta.shared::cta.b64 P1, [%0], %1, 0x989680;\n\t" \
        "@P1 bra.uni DONE_%=;\n\t"                                                    \
        "bra.uni WAIT_%=;\n\t"                                                        \
        "DONE_%=:\n\t}"                                                               \
        :: "r"(addr), "r"((uint32_t)(ph)) : "memory"); } while (0)

// ---------------- pre-pass: dtype detect ----------------
__global__ void detect_dtype_kernel(const int* __restrict__ w, long long n_words32) {
    __shared__ int ok;
    if (threadIdx.x == 0) ok = 1;
    __syncthreads();
    const long long pos = 2LL * threadIdx.x + 1;
    if (pos < n_words32) {
        const int v = w[pos];
        if (v != 0 && v != -1) ok = 0;
    }
    __syncthreads();
    if (threadIdx.x == 0) g_neigh_is64 = ok;
}

// ---------------- pre-pass: data -> packed hi|lo bf16 rows (+ zero pad row) ----------------
__global__ void convert_data_kernel(const float* __restrict__ data, int nrows) {
    const int i = blockIdx.x * blockDim.x + threadIdx.x;   // chunk id: row*8 + c
    if (i >= (nrows + 1) * 8) return;
    const int row = i >> 3, c = i & 7;
    if (row == nrows) {
        *(uint4*)(g_pack + (long long)row * 64 + c * 8) = make_uint4(0, 0, 0, 0);
        return;
    }
    const bool lo = (c >= 4);
    const int e0  = (c & 3) * 8;
    const float4* s = (const float4*)(data + (long long)row * C_IN + e0);
    const float4 f0 = s[0], f1 = s[1];
    const float v[8] = { f0.x, f0.y, f0.z, f0.w, f1.x, f1.y, f1.z, f1.w };
    __nv_bfloat16 h[8];
    #pragma unroll
    for (int j = 0; j < 8; j++) {
        const __nv_bfloat16 hh = __float2bfloat16(v[j]);
        h[j] = lo ? __float2bfloat16(v[j] - __bfloat162float(hh)) : hh;
    }
    *(uint4*)(g_pack + (long long)row * 64 + c * 8) = *(const uint4*)h;
}

// ---------------- pre-pass: smem-tiled transpose neigh -> g_nT[k][node] ----------------
__global__ void transpose_neigh_kernel(const void* __restrict__ neigh_raw, int N, int Nceil) {
    __shared__ int tile[256 * KD];                     // 27KB; stride-27 reads conflict-free
    const int base = blockIdx.x * 256;
    const bool is64 = (g_neigh_is64 != 0);
    const int*       n32 = (const int*)neigh_raw;
    const long long* n64 = (const long long*)neigh_raw;

    const long long lim = (long long)N * KD;
    for (int i = threadIdx.x; i < 256 * KD; i += 256) {   // coalesced load
        const long long e = (long long)base * KD + i;
        tile[i] = (e < lim) ? (is64 ? (int)n64[e] : n32[e]) : -1;
    }
    __syncthreads();

    const int node = base + threadIdx.x;
    if (node >= Nceil) return;
    #pragma unroll
    for (int k = 0; k < KD; k++) {                        // coalesced writes per k
        const int v = tile[threadIdx.x * KD + k];
        g_nT[k * MAXN + node] = ((v >= 0 && v < N) ? v : N) << 7;
    }
}

// ---------------- pre-pass: weights -> B fragments (m16n8k16 layout) ----------------
__global__ void convert_bfrag_kernel(const float* __restrict__ w) {
    const int i = blockIdx.x * blockDim.x + threadIdx.x;   // (k, f, lane)
    if (i >= KD * 16 * 32) return;
    const int lane = i & 31, f = (i >> 5) & 15, k = i >> 9;
    const int nt = f & 3, s = (f >> 2) & 1, v = f >> 3;
    const int n  = nt * 8 + (lane >> 2);
    const int r0 = (lane & 3) * 2;
    const int rows[4] = { r0, r0 + 1, r0 + 8, r0 + 9 };
    uint16_t h[4];
    #pragma unroll
    for (int j = 0; j < 4; j++) {
        const float x = w[k * C_IN * C_OUT + (s * 16 + rows[j]) * C_OUT + n];
        const __nv_bfloat16 hi = __float2bfloat16(x);
        const __nv_bfloat16 val = (v == 0) ? hi : __float2bfloat16(x - __bfloat162float(hi));
        h[j] = *(const uint16_t*)&val;
    }
    uint2 r;
    r.x = (uint32_t)h[0] | ((uint32_t)h[1] << 16);
    r.y = (uint32_t)h[2] | ((uint32_t)h[3] << 16);
    g_bfrag[(k * 16 + f) * 32 + lane] = r;
}

// ---------------- main: cp.async-gather + HMMA 3xBF16 ----------------
__global__ __launch_bounds__(TPB) void octconv_hmma_kernel(float* __restrict__ out, int N)
{
    __shared__ __align__(256) uint8_t sA[2][TM * ARS];      // 36.9KB double A tile
    __shared__ __align__(256) uint8_t sB[2][4096];          // 8KB  B double buffer
    __shared__ __align__(8)  uint64_t smbar[2];

    const int tid  = threadIdx.x;
    const int warp = tid >> 5;
    const int lane = tid & 31;
    const int base = blockIdx.x * TM;

    const uint32_t aAddr[2] = { s2u(&sA[0][0]), s2u(&sA[1][0]) };
    const uint32_t bAddr[2] = { s2u(&sB[0][0]), s2u(&sB[1][0]) };
    const uint32_t mAddr[2] = { s2u(&smbar[0]), s2u(&smbar[1]) };

    if (tid == 0) {
        asm volatile("mbarrier.init.shared.b64 [%0], %1;" :: "r"(mAddr[0]), "r"(1u) : "memory");
        asm volatile("mbarrier.init.shared.b64 [%0], %1;" :: "r"(mAddr[1]), "r"(1u) : "memory");
    }
    __syncthreads();

    // gather mapping: 8 lanes per row; this thread: chunk c16, rows rbase + 4j
    const int c16   = (lane & 7) * 16;
    const int rbase = warp * 32 + (lane >> 3);
    const uint8_t* packb = (const uint8_t*)g_pack;

    #define ISSUE_B(k) do {                                                          \
        if (tid == 0) {                                                              \
            const int b_ = (k) & 1;                                                  \
            asm volatile("mbarrier.arrive.expect_tx.shared.b64 _, [%0], %1;"         \
                         :: "r"(mAddr[b_]), "r"(4096u) : "memory");                  \
            bulkcp(bAddr[b_], (const uint8_t*)g_bfrag + (k) * 4096, 4096, mAddr[b_]);\
        } } while (0)

    // A issue: index rows are 4 consecutive ints per warp-op -> 1 line broadcast
    #define ISSUE_A(kk) do {                                                         \
        const int* nT_ = g_nT + (kk) * MAXN + base;                                  \
        const uint32_t ab_ = aAddr[(kk) & 1];                                        \
        _Pragma("unroll")                                                            \
        for (int j = 0; j < 8; j++) {                                                \
            const int row_ = rbase + 4 * j;                                          \
            const uint32_t off_ = (uint32_t)__ldg(nT_ + row_);                       \
            cpasync16(ab_ + row_ * ARS + c16, packb + off_ + c16);                   \
        }                                                                            \
        asm volatile("cp.async.commit_group;");                                      \
    } while (0)

    float acc[2][4][4];
    #pragma unroll
    for (int mt = 0; mt < 2; mt++)
        #pragma unroll
        for (int nt = 0; nt < 4; nt++)
            #pragma unroll
            for (int e = 0; e < 4; e++) acc[mt][nt][e] = 0.0f;

    ISSUE_B(0);
    ISSUE_B(1);
    ISSUE_A(0);
    int ph0 = 0, ph1 = 0;

    for (int k = 0; k < KD; k++) {
        const int b = k & 1;
        if (k + 1 < KD) {
            ISSUE_A(k + 1);                                    // buffer b^1 freed at k-1 end
            asm volatile("cp.async.wait_group 1;" ::: "memory");
        } else {
            asm volatile("cp.async.wait_group 0;" ::: "memory");
        }
        if (warp == 0) {                                       // leader-wait for B_k
            if (b == 0) { MBAR_WAIT(mAddr[0], ph0); }
            else        { MBAR_WAIT(mAddr[1], ph1); }
        }
        if (b == 0) ph0 ^= 1; else ph1 ^= 1;
        __syncthreads();                                       // A_k + B_k visible to all

        const uint2* bf = (const uint2*)(&sB[b][0]);
        #pragma unroll
        for (int mt = 0; mt < 2; mt++) {
            const uint32_t rowoff = (uint32_t)((warp * 32 + mt * 16 + (lane & 15)) * ARS
                                               + ((lane >> 4) << 4));
            uint32_t ah0[4], ah1[4], al0[4], al1[4];
            ldsm4(ah0, aAddr[b] + rowoff + 0);    // hi, kstep0
            ldsm4(ah1, aAddr[b] + rowoff + 32);   // hi, kstep1
            ldsm4(al0, aAddr[b] + rowoff + 64);   // lo, kstep0
            ldsm4(al1, aAddr[b] + rowoff + 96);   // lo, kstep1
            #pragma unroll
            for (int nt = 0; nt < 4; nt++) {
                const uint2 bh0 = bf[(0 + nt)  * 32 + lane];
                const uint2 bh1 = bf[(4 + nt)  * 32 + lane];
                const uint2 bl0 = bf[(8 + nt)  * 32 + lane];
                const uint2 bl1 = bf[(12 + nt) * 32 + lane];
                mma16816(acc[mt][nt], ah0, bh0);   // hi*whi
                mma16816(acc[mt][nt], ah1, bh1);
                mma16816(acc[mt][nt], ah0, bl0);   // hi*wlo
                mma16816(acc[mt][nt], ah1, bl1);
                mma16816(acc[mt][nt], al0, bh0);   // lo*whi
                mma16816(acc[mt][nt], al1, bh1);
            }
        }
        __syncthreads();                          // A buffer b + B buffer b free
        if (k + 2 < KD) ISSUE_B(k + 2);
    }

    // ---- epilogue: C frags -> smem [128][34] -> coalesced store ----
    float* sg = (float*)&sA[0][0];
    #pragma unroll
    for (int mt = 0; mt < 2; mt++) {
        const int r = warp * 32 + mt * 16 + (lane >> 2);
        #pragma unroll
        for (int nt = 0; nt < 4; nt++) {
            const int c = nt * 8 + (lane & 3) * 2;
            *(float2*)(sg + r * 34 + c)       = make_float2(acc[mt][nt][0], acc[mt][nt][1]);
            *(float2*)(sg + (r + 8) * 34 + c) = make_float2(acc[mt][nt][2], acc[mt][nt][3]);
        }
    }
    __syncthreads();
    #pragma unroll 4
    for (int i = 0; i < 32; i++) {
        const int r = warp * 32 + i;
        const int node = base + r;
        if (node < N) out[(long long)node * C_OUT + lane] = sg[r * 34 + lane];
    }
}

extern "C" void kernel_launch(void* const* d_in, const int* in_sizes, int n_in,
                              void* d_out, int out_size)
{
    // Identify inputs by element count: weights=27648 (smallest); data=N*32 (largest); neigh=N*27
    long long s[3] = { (long long)in_sizes[0], (long long)in_sizes[1], (long long)in_sizes[2] };
    int iw  = (s[0] <= s[1] && s[0] <= s[2]) ? 0 : (s[1] <= s[2] ? 1 : 2);
    int idt = (s[0] >= s[1] && s[0] >= s[2]) ? 0 : (s[1] >= s[2] ? 1 : 2);
    if (iw == idt) { iw = 1; idt = 0; }
    int ing = 3 - iw - idt;

    const float* data    = (const float*)d_in[idt];
    const float* weights = (const float*)d_in[iw];
    const void*  neigh   = d_in[ing];
    float*       out     = (float*)d_out;

    const int N     = (int)(s[idt] / C_IN);
    const int grid  = (N + TM - 1) / TM;
    const int Nceil = grid * TM;

    detect_dtype_kernel<<<1, 1024>>>((const int*)neigh, s[ing]);
    convert_data_kernel<<<((N + 1) * 8 + 255) / 256, 256>>>(data, N);
    transpose_neigh_kernel<<<(Nceil + 255) / 256, 256>>>(neigh, N, Nceil);
    convert_bfrag_kernel<<<(KD * 16 * 32 + 255) / 256, 256>>>(weights);
    octconv_hmma_kernel<<<grid, TPB>>>(out, N);
}

// round 14
// speedup vs baseline: 1.2295x; 1.2295x over previous
#include <cuda_runtime.h>
#include <cuda_bf16.h>
#include <stdint.h>

#define C_IN   32
#define C_OUT  32
#define KD     27
#define TPB    128
#define TM     128
#define MAXN   262144
#define ARS    144                   // A row stride (bytes): conflict-free ldsm

// dynamic smem layout (bytes)
#define OFF_A(st)  ((st) * (TM * ARS))            // 2 x 18432
#define OFF_B(st)  (36864 + (st) * 4096)          // 2 x 4096
#define OFF_IDXC   45056                          // 64*27*4 = 6912 (cp-half indices)
#define OFF_MBAR   51968                          // 2 x u64
#define SMEM_TOTAL 51984
#define STAGE_TX   (64 * 128 + 4096)              // bulk bytes per stage: A-half 8KB + B 4KB

// ---------------- device scratch ----------------
__device__ __align__(256) __nv_bfloat16 g_pack[(MAXN + 1) * 64]; // [N+1][128B] hi|lo; row N zeros
__device__ __align__(256) uint2 g_bfrag[KD * 16 * 32];           // [k][frag][lane], 4KB/k
__device__ int g_neigh_is64;

// ---------------- helpers ----------------
__device__ __forceinline__ uint32_t s2u(const void* p) {
    uint32_t a;
    asm("{ .reg .u64 t; cvta.to.shared.u64 t, %1; cvt.u32.u64 %0, t; }" : "=r"(a) : "l"(p));
    return a;
}
__device__ __forceinline__ void bulkcp(uint32_t dst, const void* src, uint32_t bytes, uint32_t mbar) {
    asm volatile("cp.async.bulk.shared::cluster.global.mbarrier::complete_tx::bytes "
                 "[%0], [%1], %2, [%3];"
                 :: "r"(dst), "l"(src), "r"(bytes), "r"(mbar) : "memory");
}
__device__ __forceinline__ void cpasync16(uint32_t dst, const void* src) {
    asm volatile("cp.async.cg.shared.global [%0], [%1], 16;" :: "r"(dst), "l"(src));
}
__device__ __forceinline__ void ldsm4(uint32_t* r, uint32_t addr) {
    asm volatile("ldmatrix.sync.aligned.m8n8.x4.shared.b16 {%0,%1,%2,%3}, [%4];"
                 : "=r"(r[0]), "=r"(r[1]), "=r"(r[2]), "=r"(r[3]) : "r"(addr));
}
__device__ __forceinline__ void mma16816(float* c, const uint32_t* a, uint2 b) {
    asm volatile("mma.sync.aligned.m16n8k16.row.col.f32.bf16.bf16.f32 "
                 "{%0,%1,%2,%3}, {%4,%5,%6,%7}, {%8,%9}, {%0,%1,%2,%3};"
                 : "+f"(c[0]), "+f"(c[1]), "+f"(c[2]), "+f"(c[3])
                 : "r"(a[0]), "r"(a[1]), "r"(a[2]), "r"(a[3]), "r"(b.x), "r"(b.y));
}
#define MBAR_WAIT(addr, ph) do {                                                      \
    asm volatile("{\n\t.reg .pred P1;\n\t"                                            \
        "WAIT_%=:\n\t"                                                                \
        "mbarrier.try_wait.parity.acquire.cta.shared::cta.b64 P1, [%0], %1, 0x989680;\n\t" \
        "@P1 bra.uni DONE_%=;\n\t"                                                    \
        "bra.uni WAIT_%=;\n\t"                                                        \
        "DONE_%=:\n\t}"                                                               \
        :: "r"(addr), "r"((uint32_t)(ph)) : "memory"); } while (0)

// ---------------- pre-pass: dtype detect ----------------
__global__ void detect_dtype_kernel(const int* __restrict__ w, long long n_words32) {
    __shared__ int ok;
    if (threadIdx.x == 0) ok = 1;
    __syncthreads();
    const long long pos = 2LL * threadIdx.x + 1;
    if (pos < n_words32) {
        const int v = w[pos];
        if (v != 0 && v != -1) ok = 0;
    }
    __syncthreads();
    if (threadIdx.x == 0) g_neigh_is64 = ok;
}

// ---------------- pre-pass: data -> packed hi|lo bf16 rows (+ zero pad row) ----------------
__global__ void convert_data_kernel(const float* __restrict__ data, int nrows) {
    const int i = blockIdx.x * blockDim.x + threadIdx.x;   // chunk id: row*8 + c
    if (i >= (nrows + 1) * 8) return;
    const int row = i >> 3, c = i & 7;
    if (row == nrows) {
        *(uint4*)(g_pack + (long long)row * 64 + c * 8) = make_uint4(0, 0, 0, 0);
        return;
    }
    const bool lo = (c >= 4);
    const int e0  = (c & 3) * 8;
    const float4* s = (const float4*)(data + (long long)row * C_IN + e0);
    const float4 f0 = s[0], f1 = s[1];
    const float v[8] = { f0.x, f0.y, f0.z, f0.w, f1.x, f1.y, f1.z, f1.w };
    __nv_bfloat16 h[8];
    #pragma unroll
    for (int j = 0; j < 8; j++) {
        const __nv_bfloat16 hh = __float2bfloat16(v[j]);
        h[j] = lo ? __float2bfloat16(v[j] - __bfloat162float(hh)) : hh;
    }
    *(uint4*)(g_pack + (long long)row * 64 + c * 8) = *(const uint4*)h;
}

// ---------------- pre-pass: weights -> B fragments (m16n8k16 layout) ----------------
__global__ void convert_bfrag_kernel(const float* __restrict__ w) {
    const int i = blockIdx.x * blockDim.x + threadIdx.x;   // (k, f, lane)
    if (i >= KD * 16 * 32) return;
    const int lane = i & 31, f = (i >> 5) & 15, k = i >> 9;
    const int nt = f & 3, s = (f >> 2) & 1, v = f >> 3;
    const int n  = nt * 8 + (lane >> 2);
    const int r0 = (lane & 3) * 2;
    const int rows[4] = { r0, r0 + 1, r0 + 8, r0 + 9 };
    uint16_t h[4];
    #pragma unroll
    for (int j = 0; j < 4; j++) {
        const float x = w[k * C_IN * C_OUT + (s * 16 + rows[j]) * C_OUT + n];
        const __nv_bfloat16 hi = __float2bfloat16(x);
        const __nv_bfloat16 val = (v == 0) ? hi : __float2bfloat16(x - __bfloat162float(hi));
        h[j] = *(const uint16_t*)&val;
    }
    uint2 r;
    r.x = (uint32_t)h[0] | ((uint32_t)h[1] << 16);
    r.y = (uint32_t)h[2] | ((uint32_t)h[3] << 16);
    g_bfrag[(k * 16 + f) * 32 + lane] = r;
}

// ---------------- main: hybrid bulk+cp.async gather + HMMA 3xBF16 ----------------
__global__ __launch_bounds__(TPB) void octconv_hmma_kernel(
    const void* __restrict__ neigh_raw, float* __restrict__ out, int N)
{
    extern __shared__ __align__(256) uint8_t smem[];

    const int tid  = threadIdx.x;
    const int warp = tid >> 5;
    const int lane = tid & 31;
    const int base = blockIdx.x * TM;
    const bool is64 = (g_neigh_is64 != 0);
    const int*       n32 = (const int*)neigh_raw;
    const long long* n64 = (const long long*)neigh_raw;

    const uint32_t smemb  = s2u(smem);
    const uint32_t aAddr[2] = { smemb + OFF_A(0), smemb + OFF_A(1) };
    const uint32_t bAddr[2] = { smemb + OFF_B(0), smemb + OFF_B(1) };
    const uint32_t mAddr[2] = { smemb + OFF_MBAR, smemb + OFF_MBAR + 8 };
    int* sidxc = (int*)(smem + OFF_IDXC);          // [64 rows][27] for cp-half

    if (tid == 0) {
        asm volatile("mbarrier.init.shared.b64 [%0], %1;" :: "r"(mAddr[0]), "r"(1u) : "memory");
        asm volatile("mbarrier.init.shared.b64 [%0], %1;" :: "r"(mAddr[1]), "r"(1u) : "memory");
    }

    // ---- coalesced index staging through A area (free pre-pipeline) ----
    {
        int* tmp = (int*)smem;                     // [128 rows][27], 13824B < 18432B
        const long long lim = (long long)N * KD;
        #pragma unroll
        for (int i = tid; i < TM * KD; i += TPB) {
            const long long e = (long long)base * KD + i;
            int v = -1;
            if (e < lim) v = is64 ? (int)n64[e] : n32[e];
            tmp[i] = ((v >= 0 && v < N) ? v : N) << 7;   // byte offset into g_pack
        }
        __syncthreads();
        // cp-half rows 64..127 -> persistent sidxc
        #pragma unroll
        for (int i = tid; i < 64 * KD; i += TPB) sidxc[i] = tmp[64 * KD + i];
    }
    uint32_t aoff[KD];                             // bulk-half: row == tid (tid < 64)
    {
        const int* tmp = (const int*)smem;
        if (tid < 64) {
            #pragma unroll
            for (int j = 0; j < KD; j++) aoff[j] = (uint32_t)tmp[tid * KD + j];
        }
        __syncthreads();                           // done reading tmp before A writes
    }

    float acc[2][4][4];
    #pragma unroll
    for (int mt = 0; mt < 2; mt++)
        #pragma unroll
        for (int nt = 0; nt < 4; nt++)
            #pragma unroll
            for (int e = 0; e < 4; e++) acc[mt][nt][e] = 0.0f;

    const uint8_t* packb = (const uint8_t*)g_pack;
    const int c16 = (lane & 7) * 16;               // chunk within row (cp half)
    const int rr0 = 64 + (tid >> 3);               // first cp row for this thread

    #define ISSUE(k) do {                                                            \
        const int b_ = (k) & 1;                                                      \
        const uint32_t ab_ = aAddr[b_];                                              \
        if (tid == 0) {                                                              \
            asm volatile("mbarrier.arrive.expect_tx.shared.b64 _, [%0], %1;"         \
                         :: "r"(mAddr[b_]), "r"((uint32_t)STAGE_TX) : "memory");     \
            bulkcp(bAddr[b_], (const uint8_t*)g_bfrag + (k) * 4096, 4096, mAddr[b_]);\
        }                                                                            \
        if (tid < 64)                                                                \
            bulkcp(ab_ + tid * ARS, packb + aoff[(k)], 128, mAddr[b_]);              \
        _Pragma("unroll")                                                            \
        for (int j_ = 0; j_ < 4; j_++) {                                             \
            const int row_ = rr0 + 16 * j_;                                          \
            const uint32_t off_ = (uint32_t)sidxc[(row_ - 64) * KD + (k)];           \
            cpasync16(ab_ + row_ * ARS + c16, packb + off_ + c16);                   \
        }                                                                            \
        asm volatile("cp.async.commit_group;");                                      \
    } while (0)

    ISSUE(0);
    int ph0 = 0, ph1 = 0;

    for (int k = 0; k < KD; k++) {
        const int b = k & 1;
        if (k + 1 < KD) {
            ISSUE(k + 1);                                  // buffer b^1 freed at end of k-1
            asm volatile("cp.async.wait_group 1;" ::: "memory");
        } else {
            asm volatile("cp.async.wait_group 0;" ::: "memory");
        }
        if (warp == 0) {                                   // leader-wait for bulk half + B
            if (b == 0) { MBAR_WAIT(mAddr[0], ph0); }
            else        { MBAR_WAIT(mAddr[1], ph1); }
        }
        if (b == 0) ph0 ^= 1; else ph1 ^= 1;
        __syncthreads();                                   // A_k + B_k visible to all

        const uint2* bf = (const uint2*)(smem + OFF_B(b));
        #pragma unroll
        for (int mt = 0; mt < 2; mt++) {
            const uint32_t rowoff = (uint32_t)((warp * 32 + mt * 16 + (lane & 15)) * ARS
                                               + ((lane >> 4) << 4));
            uint32_t ah0[4], ah1[4], al0[4], al1[4];
            ldsm4(ah0, aAddr[b] + rowoff + 0);    // hi, kstep0
            ldsm4(ah1, aAddr[b] + rowoff + 32);   // hi, kstep1
            ldsm4(al0, aAddr[b] + rowoff + 64);   // lo, kstep0
            ldsm4(al1, aAddr[b] + rowoff + 96);   // lo, kstep1
            #pragma unroll
            for (int nt = 0; nt < 4; nt++) {
                const uint2 bh0 = bf[(0 + nt)  * 32 + lane];
                const uint2 bh1 = bf[(4 + nt)  * 32 + lane];
                const uint2 bl0 = bf[(8 + nt)  * 32 + lane];
                const uint2 bl1 = bf[(12 + nt) * 32 + lane];
                mma16816(acc[mt][nt], ah0, bh0);   // hi*whi
                mma16816(acc[mt][nt], ah1, bh1);
                mma16816(acc[mt][nt], ah0, bl0);   // hi*wlo
                mma16816(acc[mt][nt], ah1, bl1);
                mma16816(acc[mt][nt], al0, bh0);   // lo*whi
                mma16816(acc[mt][nt], al1, bh1);
            }
        }
        __syncthreads();                          // A/B buffer b free for stage k+2
    }

    // ---- epilogue: C frags -> smem [128][34] -> coalesced store ----
    float* sg = (float*)smem;
    #pragma unroll
    for (int mt = 0; mt < 2; mt++) {
        const int r = warp * 32 + mt * 16 + (lane >> 2);
        #pragma unroll
        for (int nt = 0; nt < 4; nt++) {
            const int c = nt * 8 + (lane & 3) * 2;
            *(float2*)(sg + r * 34 + c)       = make_float2(acc[mt][nt][0], acc[mt][nt][1]);
            *(float2*)(sg + (r + 8) * 34 + c) = make_float2(acc[mt][nt][2], acc[mt][nt][3]);
        }
    }
    __syncthreads();
    #pragma unroll 4
    for (int i = 0; i < 32; i++) {
        const int r = warp * 32 + i;
        const int node = base + r;
        if (node < N) out[(long long)node * C_OUT + lane] = sg[r * 34 + lane];
    }
}

extern "C" void kernel_launch(void* const* d_in, const int* in_sizes, int n_in,
                              void* d_out, int out_size)
{
    // Identify inputs by element count: weights=27648 (smallest); data=N*32 (largest); neigh=N*27
    long long s[3] = { (long long)in_sizes[0], (long long)in_sizes[1], (long long)in_sizes[2] };
    int iw  = (s[0] <= s[1] && s[0] <= s[2]) ? 0 : (s[1] <= s[2] ? 1 : 2);
    int idt = (s[0] >= s[1] && s[0] >= s[2]) ? 0 : (s[1] >= s[2] ? 1 : 2);
    if (iw == idt) { iw = 1; idt = 0; }
    int ing = 3 - iw - idt;

    const float* data    = (const float*)d_in[idt];
    const float* weights = (const float*)d_in[iw];
    const void*  neigh   = d_in[ing];
    float*       out     = (float*)d_out;

    const int N = (int)(s[idt] / C_IN);

    static int smem_set = 0;
    if (!smem_set) {
        cudaFuncSetAttribute(octconv_hmma_kernel,
                             cudaFuncAttributeMaxDynamicSharedMemorySize, SMEM_TOTAL);
        smem_set = 1;
    }

    detect_dtype_kernel<<<1, 1024>>>((const int*)neigh, s[ing]);
    convert_data_kernel<<<((N + 1) * 8 + 255) / 256, 256>>>(data, N);
    convert_bfrag_kernel<<<(KD * 16 * 32 + 255) / 256, 256>>>(weights);
    octconv_hmma_kernel<<<(N + TM - 1) / TM, TPB, SMEM_TOTAL>>>(neigh, out, N);
}